// round 1
// baseline (speedup 1.0000x reference)
#include <cuda_runtime.h>
#include <math.h>

#define MAX_N      16
#define NBINS      4096
#define CAND_MAX   16384
#define HIST_THREADS 256
#define HIST_ITER    16
#define CHUNK (HIST_THREADS * HIST_ITER)   // 4096 elements per block

__device__ unsigned int       g_hist[MAX_N * NBINS];
__device__ int                g_count[MAX_N];
__device__ int                g_thresh[MAX_N];
__device__ unsigned long long g_cand[MAX_N * CAND_MAX];

__device__ __forceinline__ unsigned int mono_f32(float f) {
    unsigned int u = __float_as_uint(f);
    return (u & 0x80000000u) ? ~u : (u | 0x80000000u);
}

// ---------------------------------------------------------------------------
// Pass 1: per-batch 12-bit histogram of monotone score keys
// grid: (ceil(A/CHUNK), N), block: 256
// ---------------------------------------------------------------------------
__global__ void hist_kernel(const float* __restrict__ scores, int A) {
    __shared__ unsigned int sh[NBINS];
    const int b = blockIdx.y;
    for (int i = threadIdx.x; i < NBINS; i += blockDim.x) sh[i] = 0;
    __syncthreads();

    const size_t batch_base = (size_t)b * (size_t)A;
    const int block_base = blockIdx.x * CHUNK;
#pragma unroll
    for (int it = 0; it < HIST_ITER; it++) {
        int off = block_base + it * HIST_THREADS + threadIdx.x;
        if (off < A) {
            unsigned int m = mono_f32(scores[batch_base + off]);
            atomicAdd(&sh[m >> 20], 1u);
        }
    }
    __syncthreads();
    for (int i = threadIdx.x; i < NBINS; i += blockDim.x) {
        unsigned int c = sh[i];
        if (c) atomicAdd(&g_hist[b * NBINS + i], c);
    }
}

// ---------------------------------------------------------------------------
// Pass 2: find per-batch threshold bin T = max b with suffix_count(b) >= k
// grid: (N), block: 256
// ---------------------------------------------------------------------------
__global__ void thresh_kernel(int k) {
    const int b = blockIdx.x;
    const int t = threadIdx.x;   // 0..255, each owns 16 bins
    __shared__ unsigned int h[NBINS];
    __shared__ unsigned int tmp[256];

    for (int i = t; i < NBINS; i += 256) h[i] = g_hist[b * NBINS + i];
    __syncthreads();

    unsigned int s = 0;
#pragma unroll
    for (int j = 0; j < 16; j++) s += h[t * 16 + j];
    tmp[t] = s;
    __syncthreads();

    // inclusive suffix sum over 256 segment sums (Hillis-Steele)
    for (int d = 1; d < 256; d <<= 1) {
        unsigned int v = (t + d < 256) ? tmp[t + d] : 0u;
        __syncthreads();
        tmp[t] += v;
        __syncthreads();
    }

    unsigned int sufMine = tmp[t];
    unsigned int sufNext = (t + 1 < 256) ? tmp[t + 1] : 0u;
    if (sufMine >= (unsigned int)k && sufNext < (unsigned int)k) {
        unsigned int acc = sufNext;
        int T = t * 16;
        for (int j = 15; j >= 0; j--) {
            acc += h[t * 16 + j];
            if (acc >= (unsigned int)k) { T = t * 16 + j; break; }
        }
        g_thresh[b] = T;
    }
}

// ---------------------------------------------------------------------------
// Pass 3: compact candidates (key12 >= T) into per-batch buffers
// grid: (ceil(A/CHUNK), N), block: 256
// ---------------------------------------------------------------------------
__global__ void compact_kernel(const float* __restrict__ scores, int A) {
    const int b = blockIdx.y;
    __shared__ int sT;
    if (threadIdx.x == 0) sT = g_thresh[b];
    __syncthreads();
    const int T = sT;

    const size_t batch_base = (size_t)b * (size_t)A;
    const int block_base = blockIdx.x * CHUNK;
#pragma unroll
    for (int it = 0; it < HIST_ITER; it++) {
        int off = block_base + it * HIST_THREADS + threadIdx.x;
        if (off < A) {
            unsigned int m = mono_f32(scores[batch_base + off]);
            if ((int)(m >> 20) >= T) {
                int pos = atomicAdd(&g_count[b], 1);
                if (pos < CAND_MAX) {
                    g_cand[b * CAND_MAX + pos] =
                        ((unsigned long long)m << 32) |
                        (unsigned long long)(0xFFFFFFFFu - (unsigned int)off);
                }
            }
        }
    }
}

// ---------------------------------------------------------------------------
// Pass 4: per-batch bitonic sort of candidates + gather + decode + write
// grid: (N), block: 1024, dyn smem = CAND_MAX * 8 bytes
// ---------------------------------------------------------------------------
__global__ void sort_decode_kernel(const float* __restrict__ scores,
                                   const float* __restrict__ anchors,
                                   const float* __restrict__ breg,
                                   float* __restrict__ out,
                                   int A, int k) {
    extern __shared__ unsigned long long s[];
    const int b = blockIdx.x;
    int C = g_count[b];
    if (C > CAND_MAX) C = CAND_MAX;
    int P = 2;
    while (P < C) P <<= 1;

    for (int i = threadIdx.x; i < P; i += blockDim.x)
        s[i] = (i < C) ? g_cand[b * CAND_MAX + i] : 0ull;
    __syncthreads();

    // bitonic sort, descending
    for (unsigned int kk = 2; kk <= (unsigned int)P; kk <<= 1) {
        for (unsigned int jj = kk >> 1; jj > 0; jj >>= 1) {
            for (unsigned int i = threadIdx.x; i < (unsigned int)P; i += blockDim.x) {
                unsigned int ixj = i ^ jj;
                if (ixj > i) {
                    unsigned long long a = s[i], c = s[ixj];
                    bool desc = ((i & kk) == 0);
                    if (desc ? (a < c) : (a > c)) { s[i] = c; s[ixj] = a; }
                }
            }
            __syncthreads();
        }
    }

    const float CLIP = 4.135166556742356f;  // log(1000/16)
    const size_t batch_base = (size_t)b * (size_t)A;

    for (int i = threadIdx.x; i < k; i += blockDim.x) {
        unsigned long long key = s[i];
        unsigned int idx = 0xFFFFFFFFu - (unsigned int)(key & 0xFFFFFFFFull);
        size_t base4 = (batch_base + idx) * 4;

        float4 box = *(const float4*)(anchors + base4);
        float4 rc  = *(const float4*)(breg + base4);

        float w  = box.z - box.x + 1.0f;
        float h  = box.w - box.y + 1.0f;
        float cx = box.x + 0.5f * w;
        float cy = box.y + 0.5f * h;

        float dw = fminf(rc.z, CLIP);
        float dh = fminf(rc.w, CLIP);

        float pcx = rc.x * w + cx;
        float pcy = rc.y * h + cy;
        float pw  = expf(dw) * w;
        float ph  = expf(dh) * h;

        float x1 = pcx - 0.5f * pw;
        float y1 = pcy - 0.5f * ph;
        float x2 = pcx + 0.5f * pw - 1.0f;
        float y2 = pcy + 0.5f * ph - 1.0f;
        float sc = scores[batch_base + idx];

        float* o = out + ((size_t)b * k + i) * 5;
        o[0] = x1; o[1] = y1; o[2] = x2; o[3] = y2; o[4] = sc;
    }
}

// ---------------------------------------------------------------------------
extern "C" void kernel_launch(void* const* d_in, const int* in_sizes, int n_in,
                              void* d_out, int out_size) {
    const float* anchors    = (const float*)d_in[0];
    const float* objectness = (const float*)d_in[1];
    const float* breg       = (const float*)d_in[2];
    float* out = (float*)d_out;

    const int NA = in_sizes[1];          // N * A
    int k = 2000;
    int N = out_size / (k * 5);
    int A = NA / N;
    if (A < k) {                         // defensive; not expected for this shape
        // out_size = N * A * 5 when A < 2000
        // solve: N = NA / A with k = A -> N*A*5 = out_size and N*A = NA
        k = (out_size * 1) / (NA / 1) ;  // 5*NA/out? fallback below
        k = (5 * NA == out_size * 1) ? NA : 2000; // keep simple; shapes are fixed
        N = out_size / (k * 5);
        A = NA / N;
    }

    void* hptr = nullptr; void* cptr = nullptr;
    cudaGetSymbolAddress(&hptr, g_hist);
    cudaGetSymbolAddress(&cptr, g_count);
    cudaMemsetAsync(hptr, 0, sizeof(unsigned int) * MAX_N * NBINS);
    cudaMemsetAsync(cptr, 0, sizeof(int) * MAX_N);

    int blocks_x = (A + CHUNK - 1) / CHUNK;
    dim3 grid(blocks_x, N);

    hist_kernel<<<grid, HIST_THREADS>>>(objectness, A);
    thresh_kernel<<<N, 256>>>(k);
    compact_kernel<<<grid, HIST_THREADS>>>(objectness, A);

    static bool attr_set = false;
    if (!attr_set) {
        cudaFuncSetAttribute(sort_decode_kernel,
                             cudaFuncAttributeMaxDynamicSharedMemorySize,
                             CAND_MAX * (int)sizeof(unsigned long long));
        attr_set = true;
    }
    sort_decode_kernel<<<N, 1024, CAND_MAX * sizeof(unsigned long long)>>>(
        objectness, anchors, breg, out, A, k);
}

// round 2
// speedup vs baseline: 1.4730x; 1.4730x over previous
#include <cuda_runtime.h>
#include <math.h>

#define MAX_N    16
#define NBINS    4096
#define CAND_MAX 4096
#define BT_MAX   16384
#define HT       512     // threads for sweep kernels
#define BPB      18      // blocks per batch for sweep kernels (18*8=144 ~ one wave)

__device__ unsigned int       g_hist[MAX_N * NBINS];
__device__ unsigned int       g_subhist[MAX_N * NBINS];
__device__ int                g_count[MAX_N];     // # candidates with bin > T (always < k)
__device__ int                g_btcount[MAX_N];   // # elements in bin == T
__device__ int                g_T[MAX_N];
__device__ int                g_S[MAX_N];         // count strictly above bin T
__device__ unsigned long long g_cand[MAX_N * CAND_MAX];
__device__ unsigned long long g_binT[MAX_N * BT_MAX];

__device__ __forceinline__ unsigned int mono_f32(float f) {
    unsigned int u = __float_as_uint(f);
    return (u & 0x80000000u) ? ~u : (u | 0x80000000u);
}
__device__ __forceinline__ float inv_mono(unsigned int m) {
    unsigned int u = (m & 0x80000000u) ? (m & 0x7FFFFFFFu) : ~m;
    return __uint_as_float(u);
}

// ---------------------------------------------------------------------------
// Pass 1: per-batch 12-bit histogram of monotone score keys (float4 sweep)
// ---------------------------------------------------------------------------
__global__ void hist_kernel(const float* __restrict__ scores, int A) {
    __shared__ unsigned int sh[NBINS];
    const int b = blockIdx.y;
    for (int i = threadIdx.x; i < NBINS; i += HT) sh[i] = 0;
    __syncthreads();

    const size_t base = (size_t)b * (size_t)A;
    if ((A & 3) == 0) {
        const float4* s4 = (const float4*)(scores + base);
        const int A4 = A >> 2;
        for (int i = blockIdx.x * HT + threadIdx.x; i < A4; i += BPB * HT) {
            float4 v = s4[i];
            atomicAdd(&sh[mono_f32(v.x) >> 20], 1u);
            atomicAdd(&sh[mono_f32(v.y) >> 20], 1u);
            atomicAdd(&sh[mono_f32(v.z) >> 20], 1u);
            atomicAdd(&sh[mono_f32(v.w) >> 20], 1u);
        }
    } else {
        for (int i = blockIdx.x * HT + threadIdx.x; i < A; i += BPB * HT)
            atomicAdd(&sh[mono_f32(scores[base + i]) >> 20], 1u);
    }
    __syncthreads();
    for (int i = threadIdx.x; i < NBINS; i += HT) {
        unsigned int c = sh[i];
        if (c) atomicAdd(&g_hist[b * NBINS + i], c);
    }
}

// ---------------------------------------------------------------------------
// Pass 2: per-batch threshold bin T (max bin with suffix >= k), S = suffix(T+1).
// Also zeroes the per-batch counters + sub-histogram for this replay.
// ---------------------------------------------------------------------------
__global__ void thresh_kernel(int k) {
    const int b = blockIdx.x;
    const int t = threadIdx.x;   // 256 threads, 16 bins each
    __shared__ unsigned int h[NBINS];
    __shared__ unsigned int tmp[256];

    for (int i = t; i < NBINS; i += 256) {
        h[i] = g_hist[b * NBINS + i];
        g_subhist[b * NBINS + i] = 0;
    }
    if (t == 0) { g_count[b] = 0; g_btcount[b] = 0; }
    __syncthreads();

    unsigned int s = 0;
#pragma unroll
    for (int j = 0; j < 16; j++) s += h[t * 16 + j];
    tmp[t] = s;
    __syncthreads();

    for (int d = 1; d < 256; d <<= 1) {
        unsigned int v = (t + d < 256) ? tmp[t + d] : 0u;
        __syncthreads();
        tmp[t] += v;
        __syncthreads();
    }

    unsigned int sufMine = tmp[t];
    unsigned int sufNext = (t + 1 < 256) ? tmp[t + 1] : 0u;
    if (sufMine >= (unsigned int)k && sufNext < (unsigned int)k) {
        unsigned int acc = sufNext;
        for (int j = 15; j >= 0; j--) {
            unsigned int c = h[t * 16 + j];
            if (acc + c >= (unsigned int)k) {
                g_T[b] = t * 16 + j;
                g_S[b] = (int)acc;        // strictly-above count, < k
                break;
            }
            acc += c;
        }
    }
}

// ---------------------------------------------------------------------------
// Pass 3: compact. bin > T -> g_cand; bin == T -> g_binT + sub-histogram
// of key bits [8,20). float4 sweep.
// ---------------------------------------------------------------------------
__device__ __forceinline__ void compact_one(unsigned int m, unsigned int off,
                                            int b, int T) {
    int bin = (int)(m >> 20);
    if (bin < T) return;
    unsigned long long key = ((unsigned long long)m << 32) |
                             (unsigned long long)(0xFFFFFFFFu - off);
    if (bin > T) {
        int p = atomicAdd(&g_count[b], 1);
        if (p < CAND_MAX) g_cand[b * CAND_MAX + p] = key;
    } else {
        atomicAdd(&g_subhist[b * NBINS + ((m >> 8) & 0xFFFu)], 1u);
        int p = atomicAdd(&g_btcount[b], 1);
        if (p < BT_MAX) g_binT[b * BT_MAX + p] = key;
    }
}

__global__ void compact_kernel(const float* __restrict__ scores, int A) {
    const int b = blockIdx.y;
    __shared__ int sT;
    if (threadIdx.x == 0) sT = g_T[b];
    __syncthreads();
    const int T = sT;
    const size_t base = (size_t)b * (size_t)A;

    if ((A & 3) == 0) {
        const float4* s4 = (const float4*)(scores + base);
        const int A4 = A >> 2;
        for (int i = blockIdx.x * HT + threadIdx.x; i < A4; i += BPB * HT) {
            float4 v = s4[i];
            unsigned int o = (unsigned int)(i << 2);
            compact_one(mono_f32(v.x), o + 0u, b, T);
            compact_one(mono_f32(v.y), o + 1u, b, T);
            compact_one(mono_f32(v.z), o + 2u, b, T);
            compact_one(mono_f32(v.w), o + 3u, b, T);
        }
    } else {
        for (int i = blockIdx.x * HT + threadIdx.x; i < A; i += BPB * HT)
            compact_one(mono_f32(scores[base + i]), (unsigned int)i, b, T);
    }
}

// ---------------------------------------------------------------------------
// Pass 4: per-batch — refine sub-threshold T2, build ~k candidates, bitonic
// sort P<=4096 (typically 2048), gather + decode + write.
// dyn smem: 4096 * 8B (keys, aliased as sub-hist during phase A)
// ---------------------------------------------------------------------------
__global__ void sort_decode_kernel(const float* __restrict__ anchors,
                                   const float* __restrict__ breg,
                                   float* __restrict__ out,
                                   int A, int k) {
    extern __shared__ unsigned long long s[];
    __shared__ unsigned int tmp[1024];
    __shared__ int sT2, sCnt;
    const int b = blockIdx.x;
    const int t = threadIdx.x;

    // ---- Phase A: refined 24-bit threshold (sub-bin within bin T) ----
    unsigned int* shist = (unsigned int*)s;   // alias keys region
    for (int i = t; i < NBINS; i += 1024) shist[i] = g_subhist[b * NBINS + i];
    const int S  = g_S[b];
    const int k2 = k - S;                     // >= 1 by construction
    __syncthreads();

    unsigned int seg = shist[t * 4] + shist[t * 4 + 1] +
                       shist[t * 4 + 2] + shist[t * 4 + 3];
    tmp[t] = seg;
    __syncthreads();
    for (int d = 1; d < 1024; d <<= 1) {
        unsigned int v = (t + d < 1024) ? tmp[t + d] : 0u;
        __syncthreads();
        tmp[t] += v;
        __syncthreads();
    }
    unsigned int sufMine = tmp[t];
    unsigned int sufNext = (t + 1 < 1024) ? tmp[t + 1] : 0u;
    if (sufMine >= (unsigned int)k2 && sufNext < (unsigned int)k2) {
        unsigned int acc = sufNext;
        for (int j = 3; j >= 0; j--) {
            unsigned int c = shist[t * 4 + j];
            if (acc + c >= (unsigned int)k2) { sT2 = t * 4 + j; break; }
            acc += c;
        }
    }
    __syncthreads();
    const int T2 = sT2;
    const int C  = min(g_count[b], CAND_MAX);
    const int BT = min(g_btcount[b], BT_MAX);
    if (t == 0) sCnt = C;
    __syncthreads();   // all shist reads done; safe to overwrite s[]

    // ---- Phase B: assemble candidate list (~k entries) ----
    for (int i = t; i < C; i += 1024) s[i] = g_cand[b * CAND_MAX + i];
    for (int i = t; i < BT; i += 1024) {
        unsigned long long key = g_binT[b * BT_MAX + i];
        if ((int)((key >> 40) & 0xFFFull) >= T2) {
            int p = atomicAdd(&sCnt, 1);
            if (p < 4096) s[p] = key;
        }
    }
    __syncthreads();
    int Ct = sCnt; if (Ct > 4096) Ct = 4096;
    int P = 2048;
    while (P < Ct) P <<= 1;                   // at most 4096
    for (int i = t; i < P; i += 1024)
        if (i >= Ct) s[i] = 0ull;             // real keys are never 0
    __syncthreads();

    // ---- Phase C: bitonic sort, descending ----
    for (unsigned int kk = 2; kk <= (unsigned int)P; kk <<= 1) {
        for (unsigned int jj = kk >> 1; jj > 0; jj >>= 1) {
            for (unsigned int i = t; i < (unsigned int)P; i += 1024) {
                unsigned int ixj = i ^ jj;
                if (ixj > i) {
                    unsigned long long a = s[i], c2 = s[ixj];
                    bool desc = ((i & kk) == 0);
                    if (desc ? (a < c2) : (a > c2)) { s[i] = c2; s[ixj] = a; }
                }
            }
            __syncthreads();
        }
    }

    // ---- Phase D: gather + decode + write ----
    const float CLIP = 4.135166556742356f;    // log(1000/16)
    const size_t base = (size_t)b * (size_t)A;
    for (int i = t; i < k; i += 1024) {
        unsigned long long key = s[i];
        unsigned int idx = 0xFFFFFFFFu - (unsigned int)(key & 0xFFFFFFFFull);
        float sc = inv_mono((unsigned int)(key >> 32));
        size_t g4 = (base + (size_t)idx) * 4;

        float4 box = *(const float4*)(anchors + g4);
        float4 rc  = *(const float4*)(breg + g4);

        float w  = box.z - box.x + 1.0f;
        float h  = box.w - box.y + 1.0f;
        float cx = box.x + 0.5f * w;
        float cy = box.y + 0.5f * h;

        float dw = fminf(rc.z, CLIP);
        float dh = fminf(rc.w, CLIP);

        float pcx = rc.x * w + cx;
        float pcy = rc.y * h + cy;
        float pw  = expf(dw) * w;
        float ph  = expf(dh) * h;

        float* o = out + ((size_t)b * k + i) * 5;
        o[0] = pcx - 0.5f * pw;
        o[1] = pcy - 0.5f * ph;
        o[2] = pcx + 0.5f * pw - 1.0f;
        o[3] = pcy + 0.5f * ph - 1.0f;
        o[4] = sc;
    }
}

// ---------------------------------------------------------------------------
extern "C" void kernel_launch(void* const* d_in, const int* in_sizes, int n_in,
                              void* d_out, int out_size) {
    const float* anchors    = (const float*)d_in[0];
    const float* objectness = (const float*)d_in[1];
    const float* breg       = (const float*)d_in[2];
    float* out = (float*)d_out;

    const int NA = in_sizes[1];
    const int k  = 2000;
    const int N  = out_size / (k * 5);
    const int A  = NA / N;

    void* hptr = nullptr;
    cudaGetSymbolAddress(&hptr, g_hist);
    cudaMemsetAsync(hptr, 0, sizeof(unsigned int) * (size_t)N * NBINS);

    dim3 grid(BPB, N);
    hist_kernel<<<grid, HT>>>(objectness, A);
    thresh_kernel<<<N, 256>>>(k);
    compact_kernel<<<grid, HT>>>(objectness, A);
    sort_decode_kernel<<<N, 1024, 4096 * sizeof(unsigned long long)>>>(
        anchors, breg, out, A, k);
}